// round 11
// baseline (speedup 1.0000x reference)
#include <cuda_runtime.h>

// EPLoss edit-probability DP. B=128, n_y=512, n_T=128, C=128. EOS = 1.
//
// R8: single-warp version was issue-bound on one SMSP (~56 instr/step).
// Split each batch item across 2 warps (2 rows/lane each), pipelined with a
// fixed skew DSKEW=40 steps. Warp 0 (rows 0..63) stages coefficient rows via
// cp.async and writes its row-63 boundary to smem bnd[]; warp 1 (rows 64..127)
// reads bnd[] for its lane 0. __syncthreads() every KSTEP=8 steps orders the
// handoff (bnd[j] written 9 global steps before it is read -> always >=1
// barrier in between). Per-warp phases: ramp [0,32) / steady [32,512) /
// epilogue [512,544), each block (8 steps) phase-pure since all boundaries
// and DSKEW are multiples of 8.

#define NY 512
#define NT 128
#define CC 128
#define RINGN 128
#define PADW 132                  // 128 data + 4 zero pad (row-0 trick)
#define PADB (PADW * 4)
#define DELTA 12                  // staging prefetch distance (columns)
#define KSTEP 8                   // steps per sync block
#define DSKEW 40                  // warp-1 lag in steps (>= 31 + KSTEP + 1)
#define LEND 544                  // local steps per warp (512 + 32)
#define GBLOCKS ((LEND + DSKEW) / KSTEP)   // 73

__global__ __launch_bounds__(64, 1)
void ep_wf2(const float* __restrict__ pred,
            const float* __restrict__ R,
            const float* __restrict__ Iins,
            const int* __restrict__ target,
            float* __restrict__ out) {
    extern __shared__ float smem[];
    float*  ringP = smem;                                  // [RINGN][PADW]: pred[b, c-1, :]
    float*  ringI = smem + RINGN * PADW;                   // [RINGN][PADW]: I[b, c, :]
    float4* Rs    = (float4*)(smem + 2 * RINGN * PADW);    // [NY]: {R0, Rins, R2, 0}
    float*  bnd   = smem + 2 * RINGN * PADW + NY * 4;      // [544]: ep[63, j]

    const int tid  = threadIdx.x;
    const int w    = tid >> 5;          // warp 0: rows 0..63, warp 1: rows 64..127
    const int lane = tid & 31;
    const int b    = blockIdx.x;

    const float* __restrict__ predb = pred + (size_t)b * NY * CC;
    const float* __restrict__ Ib    = Iins + (size_t)b * NY * CC;
    const float* __restrict__ Rb    = R    + (size_t)b * NY * 3;
    const int*   __restrict__ tgt   = target + b * NT;

    const unsigned ringPs  = (unsigned)__cvta_generic_to_shared(ringP);
    const unsigned ringIs  = (unsigned)__cvta_generic_to_shared(ringI);
    const unsigned laneOff = (unsigned)(lane * 16);
    const float* __restrict__ srcPb = predb + lane * 4;
    const float* __restrict__ srcIb = Ib + lane * 4;

    // Zero ring pad words (warp-0 lane-0 row-0 gathers read these -> 0).
    for (int k = tid; k < RINGN * 4; k += 64) {
        const int slot = k >> 2, wd = k & 3;
        ringP[slot * PADW + CC + wd] = 0.0f;
        ringI[slot * PADW + CC + wd] = 0.0f;
    }
    // Pack R as float4 rows.
    for (int j = tid; j < NY; j += 64) {
        const float r0 = Rb[3 * j + 0];
        const float r1 = Rb[3 * j + 1];
        const float r2 = Rb[3 * j + 2];
        Rs[j] = make_float4(r0, (j == NY - 1) ? 1.0f : r1, r2, 0.0f);
    }
    // Prologue staging: columns 1..DELTA-1 (warp 0 only; 1 commit group/col).
    if (w == 0) {
#pragma unroll
        for (int c = 1; c < DELTA; ++c) {
            const unsigned so = (unsigned)(c & (RINGN - 1)) * PADB + laneOff;
            const float* sP = srcPb + (c - 1) * CC;
            const float* sI = srcIb + c * CC;
            asm volatile("cp.async.cg.shared.global [%0], [%1], 16;" :: "r"(ringPs + so), "l"(sP));
            asm volatile("cp.async.cg.shared.global [%0], [%1], 16;" :: "r"(ringIs + so), "l"(sI));
            asm volatile("cp.async.commit_group;" ::: "memory");
        }
    }

    // Per-lane rows: rowa = 64w + 2*lane, rowb = rowa + 1.
    const int rowa = (w << 6) + 2 * lane;
    const int rowb = rowa + 1;
    const int ta  = (rowa == 0) ? CC : tgt[rowa - 1];  // class for row rowa's coeffs (pad for row 0)
    const int tbi = tgt[rowa];                          // class for row rowb's coeffs (= t[rowb-1])
    const bool ea = (tgt[rowa] == 1);
    const bool eb = (tgt[rowb] == 1);
    const bool isl0 = (w == 0) && (lane == 0);          // the row-0 cumprod lane

    // Column-0 coefficients: pI(i-1,1) = Rins[1] * I[b,1,t_{i-1}]
    const float rins1 = Rb[3 * 1 + 1];
    const float pI1_a = rins1 * Ib[CC + ((rowa == 0) ? 0 : tgt[rowa - 1])];
    const float pI1_b = rins1 * Ib[CC + tbi];

    __syncthreads();

    float cur0 = 0.f, cur1 = 0.f;
    float carry = 0.f;   // cur1 at end of previous step (bottom row of lane)
    float upp   = 0.f;   // previous step's upc = ep[rowa-1, j-1]
    float rpx   = 0.f;   // R0[j-1]
    float rpz   = 0.f;   // R2[j-1]

#define STAGE(S_) do {                                                          \
    const int cs_ = (S_) + DELTA;                                               \
    const int c_  = (cs_ < NY - 1) ? cs_ : (NY - 1);                            \
    const unsigned so_ = (unsigned)(cs_ & (RINGN - 1)) * PADB + laneOff;        \
    const float* sP_ = srcPb + (c_ - 1) * CC;                                   \
    const float* sI_ = srcIb + c_ * CC;                                         \
    asm volatile("cp.async.cg.shared.global [%0], [%1], 16;"                    \
                 :: "r"(ringPs + so_), "l"(sP_));                               \
    asm volatile("cp.async.cg.shared.global [%0], [%1], 16;"                    \
                 :: "r"(ringIs + so_), "l"(sI_));                               \
    asm volatile("cp.async.commit_group;" ::: "memory");                        \
} while (0)

    // Unified 2-row body for column J_>=1. Lane isl0: ga=ha=0 (pad) ->
    // n0 = cur0 * (e?1:R2[J_]) == row-0 cumprod (note R2[j], via pza select).
#define BODY(J_, UPC_) do {                                                     \
    const int slot_ = (J_) & (RINGN - 1);                                       \
    const float* __restrict__ bP_ = ringP + slot_ * PADW;                       \
    const float* __restrict__ bI_ = ringI + slot_ * PADW;                       \
    const float ga_ = bP_[ta],  gb_ = bP_[tbi];                                 \
    const float ha_ = bI_[ta],  hb_ = bI_[tbi];                                 \
    const float4 rj_ = Rs[(J_)];                                                \
    const float rins_ = rj_.y;                                                  \
    const float pza_ = isl0 ? rj_.z : rpz;                                      \
    const float pda_ = ea ? 1.0f : pza_;                                        \
    const float pdb_ = eb ? 1.0f : rpz;                                         \
    const float rga_ = rpx * ga_, rha_ = rins_ * ha_;                           \
    const float rgb_ = rpx * gb_, rhb_ = rins_ * hb_;                           \
    const float c0_ = fmaf(upp,  rga_, cur0 * pda_);                            \
    const float n0_ = fmaf((UPC_), rha_, c0_);                                  \
    const float c1_ = fmaf(cur0, rgb_, cur1 * pdb_);                            \
    const float n1_ = fmaf(n0_, rhb_, c1_);                                     \
    cur0 = n0_; cur1 = n1_; rpx = rj_.x; rpz = rj_.z;                           \
} while (0)

    // ---- warp 0 steps ----
#define STEADY0(S_) do {                                                        \
    STAGE(S_);                                                                  \
    const float upc_ = __shfl_up_sync(0xffffffffu, carry, 1);                   \
    BODY((S_) - lane, upc_);                                                    \
    upp = upc_; carry = cur1;                                                   \
    if (lane == 31) bnd[(S_) - 31] = carry;                                     \
} while (0)

#define RAMP0(S_) do {                                                          \
    STAGE(S_);                                                                  \
    const float upc_ = __shfl_up_sync(0xffffffffu, carry, 1);                   \
    const int j_ = (S_) - lane;                                                 \
    if (j_ >= 0) {                                                              \
        if (j_ == 0) {                                                          \
            cur0 = isl0 ? 1.0f : upc_ * pI1_a;                                  \
            cur1 = cur0 * pI1_b;                                                \
            const float4 r0_ = Rs[0]; rpx = r0_.x; rpz = r0_.z;                 \
        } else { BODY(j_, upc_); }                                              \
        if (lane == 31) bnd[j_] = cur1;                                         \
    }                                                                           \
    upp = upc_; carry = cur1;                                                   \
} while (0)

#define EPI0(S_) do {                                                           \
    const float upc_ = __shfl_up_sync(0xffffffffu, carry, 1);                   \
    const int j_ = (S_) - lane;                                                 \
    if (j_ < NY) {                                                              \
        BODY(j_, upc_);                                                         \
        if (lane == 31) bnd[j_] = cur1;                                         \
    }                                                                           \
    upp = upc_; carry = cur1;                                                   \
} while (0)

    // ---- warp 1 steps (lane 0 takes upc from bnd[]) ----
#define STEADY1(S_) do {                                                        \
    const float bv_ = bnd[(S_)];                                                \
    const float sh_ = __shfl_up_sync(0xffffffffu, carry, 1);                    \
    const float upc_ = (lane == 0) ? bv_ : sh_;                                 \
    BODY((S_) - lane, upc_);                                                    \
    upp = upc_; carry = cur1;                                                   \
} while (0)

#define RAMP1(S_) do {                                                          \
    const float bv_ = bnd[(S_)];                                                \
    const float sh_ = __shfl_up_sync(0xffffffffu, carry, 1);                    \
    const float upc_ = (lane == 0) ? bv_ : sh_;                                 \
    const int j_ = (S_) - lane;                                                 \
    if (j_ >= 0) {                                                              \
        if (j_ == 0) {                                                          \
            cur0 = upc_ * pI1_a;                                                \
            cur1 = cur0 * pI1_b;                                                \
            const float4 r0_ = Rs[0]; rpx = r0_.x; rpz = r0_.z;                 \
        } else { BODY(j_, upc_); }                                              \
    }                                                                           \
    upp = upc_; carry = cur1;                                                   \
} while (0)

#define EPI1(S_) do {                                                           \
    const float bv_ = bnd[(S_)];                                                \
    const float sh_ = __shfl_up_sync(0xffffffffu, carry, 1);                    \
    const float upc_ = (lane == 0) ? bv_ : sh_;                                 \
    const int j_ = (S_) - lane;                                                 \
    if (j_ < NY) { BODY(j_, upc_); }                                            \
    upp = upc_; carry = cur1;                                                   \
} while (0)

    for (int blk = 0; blk < GBLOCKS; ++blk) {
        const int ls0 = blk * KSTEP - DSKEW * w;   // this warp's local step at block start
        if (w == 0) {
            if (ls0 < LEND) {
                asm volatile("cp.async.wait_group 4;" ::: "memory");
                __syncwarp();
                if (ls0 >= 32 && ls0 < NY) {
                    STEADY0(ls0 + 0); STEADY0(ls0 + 1); STEADY0(ls0 + 2); STEADY0(ls0 + 3);
                    STEADY0(ls0 + 4); STEADY0(ls0 + 5); STEADY0(ls0 + 6); STEADY0(ls0 + 7);
                } else if (ls0 < 32) {
                    RAMP0(ls0 + 0); RAMP0(ls0 + 1); RAMP0(ls0 + 2); RAMP0(ls0 + 3);
                    RAMP0(ls0 + 4); RAMP0(ls0 + 5); RAMP0(ls0 + 6); RAMP0(ls0 + 7);
                } else {
                    EPI0(ls0 + 0); EPI0(ls0 + 1); EPI0(ls0 + 2); EPI0(ls0 + 3);
                    EPI0(ls0 + 4); EPI0(ls0 + 5); EPI0(ls0 + 6); EPI0(ls0 + 7);
                }
            }
        } else {
            if (ls0 >= 0 && ls0 < LEND) {
                if (ls0 >= 32 && ls0 < NY) {
                    STEADY1(ls0 + 0); STEADY1(ls0 + 1); STEADY1(ls0 + 2); STEADY1(ls0 + 3);
                    STEADY1(ls0 + 4); STEADY1(ls0 + 5); STEADY1(ls0 + 6); STEADY1(ls0 + 7);
                } else if (ls0 < 32) {
                    RAMP1(ls0 + 0); RAMP1(ls0 + 1); RAMP1(ls0 + 2); RAMP1(ls0 + 3);
                    RAMP1(ls0 + 4); RAMP1(ls0 + 5); RAMP1(ls0 + 6); RAMP1(ls0 + 7);
                } else {
                    EPI1(ls0 + 0); EPI1(ls0 + 1); EPI1(ls0 + 2); EPI1(ls0 + 3);
                    EPI1(ls0 + 4); EPI1(ls0 + 5); EPI1(ls0 + 6); EPI1(ls0 + 7);
                }
            }
        }
        __syncthreads();
    }

    // ep[127, 511] lives in warp 1 lane 31's cur1 (row 127, column 511).
    if (tid == 63) out[b] = cur1;
}

static const int kSmemBytes = (2 * RINGN * PADW + NY * 4 + 544) * 4;  // 145,536 B

extern "C" void kernel_launch(void* const* d_in, const int* in_sizes, int n_in,
                              void* d_out, int out_size) {
    const float* pred   = (const float*)d_in[0];
    const float* R      = (const float*)d_in[1];
    const float* Iins   = (const float*)d_in[2];
    const int*   target = (const int*)d_in[3];
    float* out = (float*)d_out;

    cudaFuncSetAttribute(ep_wf2,
                         cudaFuncAttributeMaxDynamicSharedMemorySize, kSmemBytes);

    const int B = out_size;  // 128
    ep_wf2<<<B, 64, kSmemBytes>>>(pred, R, Iins, target, out);
}

// round 12
// speedup vs baseline: 1.9788x; 1.9788x over previous
#include <cuda_runtime.h>

// EPLoss edit-probability DP, anti-diagonal wavefront, one warp per batch item.
// B=128, n_y=512, n_T=128, C=128. EOS label = 1.
//
// R11: revert the failed 2-warp split; fix R7's real limiter instead.
// R7 put a "memory" clobber on every per-step cp.async STAGE, which acted as a
// compiler scheduling fence per step -> step-serialized codegen (exposed
// LDS 29 + shfl 26 per step, CPI ~2.6). Now cp.async/commit are volatile-only
// (ordered among themselves, movable past FP/LDS), and the wait_group +
// __syncwarp fence (which keeps the clobber) runs once per 8 steps with
// DELTA=16 prefetch distance. ptxas can pipeline gathers across the 8-step
// unrolled block.

#define NY 512
#define NT 128
#define CC 128
#define RING 64          // ring slots (power of 2); overwrite margin needs DELTA <= 32
#define PADW 132         // 128 data + 4 pad floats (pad[0] == 0 used by lane 0)
#define PADB (PADW * 4)
#define DELTA 16         // prefetch distance in steps

__global__ __launch_bounds__(32, 1)
void ep_wavefront(const float* __restrict__ pred,
                  const float* __restrict__ R,
                  const float* __restrict__ Iins,
                  const int* __restrict__ target,
                  float* __restrict__ out) {
    extern __shared__ float smem[];
    float*  ringP = smem;                                // [RING][PADW]: pred[b, c-1, :]
    float*  ringI = smem + RING * PADW;                  // [RING][PADW]: I[b, c, :]
    float4* Rs    = (float4*)(smem + 2 * RING * PADW);   // [NY]: {R0, Rins, R2, 0}

    const int b    = blockIdx.x;
    const int lane = threadIdx.x;

    const float* __restrict__ predb = pred + (size_t)b * NY * CC;
    const float* __restrict__ Ib    = Iins + (size_t)b * NY * CC;
    const float* __restrict__ Rb    = R    + (size_t)b * NY * 3;
    const int*   __restrict__ tb    = target + b * NT;

    const unsigned ringPs = (unsigned)__cvta_generic_to_shared(ringP);
    const unsigned ringIs = (unsigned)__cvta_generic_to_shared(ringI);
    const unsigned laneOff = (unsigned)(lane * 16);
    const float* __restrict__ srcPb = predb + lane * 4;
    const float* __restrict__ srcIb = Ib + lane * 4;

    // Zero the pad words of every ring row (lane 0 gathers from pad -> 0).
    for (int k = lane; k < RING * 4; k += 32) {
        const int slot = k >> 2, w = k & 3;
        ringP[slot * PADW + CC + w] = 0.0f;
        ringI[slot * PADW + CC + w] = 0.0f;
    }

// NOTE: no "memory" clobber here — ordering vs the ring reads is enforced by
// the wait_group/__syncwarp fence (which does carry the clobber). Volatile
// keeps cp.async/commit ordered among themselves.
#define STAGE(S_) do {                                                          \
    const int cs_ = (S_) + DELTA;                                               \
    const int c_  = (cs_ < NY - 1) ? cs_ : (NY - 1);                            \
    const unsigned so_ = (unsigned)(cs_ & (RING - 1)) * PADB + laneOff;         \
    const float* sP_ = srcPb + (c_ - 1) * CC;                                   \
    const float* sI_ = srcIb + c_ * CC;                                         \
    asm volatile("cp.async.cg.shared.global [%0], [%1], 16;"                    \
                 :: "r"(ringPs + so_), "l"(sP_));                               \
    asm volatile("cp.async.cg.shared.global [%0], [%1], 16;"                    \
                 :: "r"(ringIs + so_), "l"(sI_));                               \
    asm volatile("cp.async.commit_group;");                                     \
} while (0)

    // Prologue staging: columns 1..DELTA-1 (one commit group per column).
#pragma unroll
    for (int c = 1; c < DELTA; ++c) {
        const unsigned so = (unsigned)(c & (RING - 1)) * PADB + laneOff;
        const float* sP = srcPb + (c - 1) * CC;
        const float* sI = srcIb + c * CC;
        asm volatile("cp.async.cg.shared.global [%0], [%1], 16;" :: "r"(ringPs + so), "l"(sP));
        asm volatile("cp.async.cg.shared.global [%0], [%1], 16;" :: "r"(ringIs + so), "l"(sI));
        asm volatile("cp.async.commit_group;");
    }

    // Pack R into shared as float4 rows.
    for (int j = lane; j < NY; j += 32) {
        const float r0 = Rb[3 * j + 0];
        const float r1 = Rb[3 * j + 1];
        const float r2 = Rb[3 * j + 2];
        Rs[j] = make_float4(r0, (j == NY - 1) ? 1.0f : r1, r2, 0.0f);
    }

    const int r0row = lane * 4;
    const int tt0 = tb[r0row + 0];
    const int tt1 = tb[r0row + 1];
    const int tt2 = tb[r0row + 2];
    const int tt3 = tb[r0row + 3];
    // Gather indices: tg0 is t_{row-1}; lane 0 points at the zero pad word.
    const int tg0 = lane ? tb[r0row - 1] : CC;
    const int tg1 = tt0, tg2 = tt1, tg3 = tt2;
    const bool e0 = (tt0 == 1), e1 = (tt1 == 1), e2 = (tt2 == 1), e3 = (tt3 == 1);
    const bool isl0 = (lane == 0);

    // Column-0 coefficients hoisted: pI(i-1, 1) = Rins[1]*I[b,1,t_{i-1}]
    const float rins1 = Rb[3 * 1 + 1];
    const float pI1_0 = rins1 * Ib[CC + (lane ? tb[r0row - 1] : 0)];  // unused on lane 0
    const float pI1_1 = rins1 * Ib[CC + tg1];
    const float pI1_2 = rins1 * Ib[CC + tg2];
    const float pI1_3 = rins1 * Ib[CC + tg3];

    __syncwarp();  // pads + Rs visible

    float cur0 = 0.f, cur1 = 0.f, cur2 = 0.f, cur3 = 0.f;
    float carry = 0.f;   // cur3 at end of previous step
    float upp   = 0.f;   // previous step's shfl result = ep[r0-1, j-1]
    float rpx   = 0.f;   // R0[j-1]
    float rpz   = 0.f;   // R2[j-1]

    // Unified j>=1 body. Lane 0: g0=h0=0 (pad word) -> n0 = cur0 * pd0 with
    // pd0 = e0 ? 1 : R2[j]  == row-0 cumprod. Chain: n_k = fmaf(n_{k-1}, rh_k, c_k).
#define BODY(J_, UPC_) do {                                                     \
    const int slotc_ = (J_) & (RING - 1);                                       \
    const float* __restrict__ bP_ = ringP + slotc_ * PADW;                      \
    const float* __restrict__ bI_ = ringI + slotc_ * PADW;                      \
    const float g0_ = bP_[tg0], g1_ = bP_[tg1], g2_ = bP_[tg2], g3_ = bP_[tg3]; \
    const float h0_ = bI_[tg0], h1_ = bI_[tg1], h2_ = bI_[tg2], h3_ = bI_[tg3]; \
    const float4 rj_ = Rs[(J_)];                                                \
    const float rins_ = rj_.y;                                                  \
    const float pz0_ = isl0 ? rj_.z : rpz;                                      \
    const float pd0_ = e0 ? 1.0f : pz0_;                                        \
    const float pd1_ = e1 ? 1.0f : rpz;                                         \
    const float pd2_ = e2 ? 1.0f : rpz;                                         \
    const float pd3_ = e3 ? 1.0f : rpz;                                         \
    const float rg0_ = rpx * g0_, rg1_ = rpx * g1_;                             \
    const float rg2_ = rpx * g2_, rg3_ = rpx * g3_;                             \
    const float rh0_ = rins_ * h0_, rh1_ = rins_ * h1_;                         \
    const float rh2_ = rins_ * h2_, rh3_ = rins_ * h3_;                         \
    const float c0_ = fmaf(upp,  rg0_, cur0 * pd0_);                            \
    const float n0_ = fmaf((UPC_), rh0_, c0_);                                  \
    const float c1_ = fmaf(cur0, rg1_, cur1 * pd1_);                            \
    const float n1_ = fmaf(n0_, rh1_, c1_);                                     \
    const float c2_ = fmaf(cur1, rg2_, cur2 * pd2_);                            \
    const float n2_ = fmaf(n1_, rh2_, c2_);                                     \
    const float c3_ = fmaf(cur2, rg3_, cur3 * pd3_);                            \
    const float n3_ = fmaf(n2_, rh3_, c3_);                                     \
    cur0 = n0_; cur1 = n1_; cur2 = n2_; cur3 = n3_;                             \
    rpx = rj_.x; rpz = rj_.z;                                                   \
} while (0)

#define RAMP_STEP(S_) do {                                                      \
    STAGE(S_);                                                                  \
    const float upc_ = __shfl_up_sync(0xffffffffu, carry, 1);                   \
    const int j_ = (S_) - lane;                                                 \
    if (j_ >= 0) {                                                              \
        if (j_ == 0) {                                                          \
            cur0 = lane ? (upc_ * pI1_0) : 1.0f;                                \
            cur1 = cur0 * pI1_1;                                                \
            cur2 = cur1 * pI1_2;                                                \
            cur3 = cur2 * pI1_3;                                                \
            const float4 r0_ = Rs[0];                                           \
            rpx = r0_.x; rpz = r0_.z;                                           \
        } else {                                                                \
            BODY(j_, upc_);                                                     \
        }                                                                       \
    }                                                                           \
    upp = upc_; carry = cur3;                                                   \
} while (0)

#define STEADY_STEP(S_) do {                                                    \
    STAGE(S_);                                                                  \
    const float upc_ = __shfl_up_sync(0xffffffffu, carry, 1);                   \
    BODY((S_) - lane, upc_);                                                    \
    upp = upc_; carry = cur3;                                                   \
} while (0)

#define EPI_STEP(S_) do {                                                       \
    const float upc_ = __shfl_up_sync(0xffffffffu, carry, 1);                   \
    const int j_ = (S_) - lane;                                                 \
    if (j_ < NY) { BODY(j_, upc_); }                                            \
    upp = upc_; carry = cur3;                                                   \
} while (0)

#define FENCE8() do {                                                           \
    asm volatile("cp.async.wait_group 8;" ::: "memory");                        \
    __syncwarp();                                                               \
} while (0)

    // Ramp-up: s in [0, 32). j = s-lane may be <0 or 0.
    for (int sb = 0; sb < 32; sb += 8) {
        FENCE8();
        RAMP_STEP(sb + 0); RAMP_STEP(sb + 1); RAMP_STEP(sb + 2); RAMP_STEP(sb + 3);
        RAMP_STEP(sb + 4); RAMP_STEP(sb + 5); RAMP_STEP(sb + 6); RAMP_STEP(sb + 7);
    }

    // Steady: s in [32, 512). All lanes j in [1, 511] — branch-free.
    for (int sb = 32; sb < NY; sb += 8) {
        FENCE8();
        STEADY_STEP(sb + 0); STEADY_STEP(sb + 1); STEADY_STEP(sb + 2); STEADY_STEP(sb + 3);
        STEADY_STEP(sb + 4); STEADY_STEP(sb + 5); STEADY_STEP(sb + 6); STEADY_STEP(sb + 7);
    }

    // Epilogue: s in [512, 544). All columns already staged; no more staging.
    asm volatile("cp.async.wait_group 0;" ::: "memory");
    __syncwarp();
    for (int s = NY; s < NY + 32; ++s) {
        EPI_STEP(s);
    }

    if (lane == 31) out[b] = cur3;
}

static const int kSmemBytes = 2 * RING * PADW * 4 + NY * 16;  // 75,776 B

extern "C" void kernel_launch(void* const* d_in, const int* in_sizes, int n_in,
                              void* d_out, int out_size) {
    const float* pred   = (const float*)d_in[0];
    const float* R      = (const float*)d_in[1];
    const float* Iins   = (const float*)d_in[2];
    const int*   target = (const int*)d_in[3];
    float* out = (float*)d_out;

    cudaFuncSetAttribute(ep_wavefront,
                         cudaFuncAttributeMaxDynamicSharedMemorySize, kSmemBytes);

    const int B = out_size;  // 128
    ep_wavefront<<<B, 32, kSmemBytes>>>(pred, R, Iins, target, out);
}